// round 13
// baseline (speedup 1.0000x reference)
#include <cuda_runtime.h>
#include <math.h>

// Problem constants
#define NIMG 8
#define CCH  3
#define HI   512
#define WI   512
#define HO   2048
#define WO   2048

__device__ __forceinline__ float sigm(float z) {
    return 1.0f / (1.0f + expf(-z));
}

__device__ __forceinline__ float2 ldcs2(const float* p) {
    return __ldcs(reinterpret_cast<const float2*>(p));
}
__device__ __forceinline__ void stcs2(float* p, float2 v) {
    __stcs(reinterpret_cast<float2*>(p), v);
}

// Single fused kernel: per-block param computation in shared memory, then
// back-to-front compositing with early termination (a fully-interior layer
// has m == 1 and overwrites everything below it).
// One thread = 2 consecutive x pixels -> warp spans 64 output px, halving the
// L1 wavefront footprint of each src gather instruction vs 4 px/thread.
// Canvas traffic (bg reads, out writes) uses streaming cache hints (.cs).
__global__ __launch_bounds__(128) void composite_kernel(
    const float* __restrict__ src,   // [8,3,512,512]
    const float* __restrict__ bg,    // [1,3,2048,2048]
    const float* __restrict__ coor,  // [8,4]
    float* __restrict__ out)         // [1,3,2048,2048]
{
    // Folded affine params: ix = ax*px + bx, iy = ay*py + by
    __shared__ float4 sprm[NIMG];

    const int ltid = threadIdx.y * 32 + threadIdx.x;
    if (ltid < NIMG) {
        const int n = ltid;
        float x = sigm(coor[4 * n + 0]) * (float)WO;
        float y = sigm(coor[4 * n + 1]) * (float)HO;
        float w = sigm(coor[4 * n + 2]) * (float)WO;
        float h = sigm(coor[4 * n + 3]) * (float)HO;
        float a  = (float)WO / (w + 1e-8f);
        float tx = (2.0f / (float)WO) * ((float)WO * 0.5f - x) * a;
        float b  = (float)HO / (h + 1e-8f);
        float ty = (2.0f / (float)HO) * ((float)HO * 0.5f - y) * b;
        // ix(px) = ((a*((2px+1)/WO - 1) + tx + 1)*WI - 1)/2  ==  ax*px + bx
        float ax = a * ((float)WI / (float)WO);
        float bx = ((a * (1.0f / (float)WO - 1.0f) + tx + 1.0f) * (float)WI - 1.0f) * 0.5f;
        float ay = b * ((float)HI / (float)HO);
        float by = ((b * (1.0f / (float)HO - 1.0f) + ty + 1.0f) * (float)HI - 1.0f) * 0.5f;
        sprm[n] = make_float4(ax, bx, ay, by);
    }
    __syncthreads();

    const int px0 = (blockIdx.x * 32 + threadIdx.x) * 2;
    const int py  = blockIdx.y * 4 + threadIdx.y;
    const int HW  = HO * WO;
    const int base = py * WO + px0;

    float A[3][2] = {{0.f,0.f},{0.f,0.f},{0.f,0.f}};
    float T[2] = {1.f, 1.f};

    const float fpy  = (float)py;
    const float fpx0 = (float)px0;

#pragma unroll
    for (int n = NIMG - 1; n >= 0; n--) {
        const float4 p = sprm[n];   // ax, bx, ay, by

        const float iy = fmaf(p.z, fpy, p.w);
        if (iy <= -1.0f || iy >= (float)HI) continue;

        // group x-range reject (ax > 0, ix monotone in px)
        const float ixA = fmaf(p.x, fpx0, p.y);
        const float ixB = p.x + ixA;     // px0 + 1
        if (ixB <= -1.0f || ixA >= (float)WI) continue;

        const float y0f = floorf(iy);
        const float wy1 = iy - y0f;
        const float wy0 = 1.0f - wy1;
        const int   y0  = (int)y0f;
        const int   y1  = y0 + 1;
        const float* sbase = src + (size_t)n * CCH * HI * WI;

        const bool interior = (iy >= 0.0f) && (iy < (float)(HI - 1)) &&
                              (ixA >= 0.0f) && (ixB < (float)(WI - 1));

        if (interior) {
            // m == 1 for both px: this layer overwrites everything below.
            const float* r0 = sbase + y0 * WI;
            const float* r1 = r0 + WI;
#pragma unroll
            for (int j = 0; j < 2; j++) {
                const float ix = (j == 0) ? ixA : ixB;
                const float x0f = floorf(ix);
                const float wx1 = ix - x0f;
                const float wx0 = 1.0f - wx1;
                const int   x0  = (int)x0f;
                const float w00 = wy0 * wx0, w10 = wy1 * wx0;
                const float w01 = wy0 * wx1, w11 = wy1 * wx1;
#pragma unroll
                for (int c = 0; c < CCH; c++) {
                    const float* rc0 = r0 + c * (HI * WI);
                    const float* rc1 = r1 + c * (HI * WI);
                    const float v00 = __ldg(rc0 + x0);
                    const float v10 = __ldg(rc1 + x0);
                    const float v01 = __ldg(rc0 + x0 + 1);
                    const float v11 = __ldg(rc1 + x0 + 1);
                    const float s = fmaf(v11, w11, fmaf(v10, w10,
                                    fmaf(v01, w01, v00 * w00)));
                    A[c][j] = fmaf(T[j], s, A[c][j]);
                }
                T[j] = 0.0f;
            }
            break;   // both px fully opaque: earlier layers + bg invisible
        } else {
            // Boundary path: full reference semantics (validity + clamps).
            const float wyv0 = (y0 >= 0 && y0 < HI) ? wy0 : 0.0f;
            const float wyv1 = (y1 >= 0 && y1 < HI) ? wy1 : 0.0f;
            const int y0c = min(max(y0, 0), HI - 1);
            const int y1c = min(max(y1, 0), HI - 1);
            const float my = wyv0 + wyv1;
            const float* r0 = sbase + y0c * WI;
            const float* r1 = sbase + y1c * WI;
#pragma unroll
            for (int j = 0; j < 2; j++) {
                const float ix = (j == 0) ? ixA : ixB;
                const float x0f = floorf(ix);
                const float wx1 = ix - x0f;
                const float wx0 = 1.0f - wx1;
                const int   x0  = (int)x0f;
                const int   x1  = x0 + 1;
                const float wxv0 = (x0 >= 0 && x0 < WI) ? wx0 : 0.0f;
                const float wxv1 = (x1 >= 0 && x1 < WI) ? wx1 : 0.0f;
                const int x0c = min(max(x0, 0), WI - 1);
                const int x1c = min(max(x1, 0), WI - 1);

                const float m = my * (wxv0 + wxv1);
                if (m == 0.0f) continue;
                const float wgt = T[j] * m;
#pragma unroll
                for (int c = 0; c < CCH; c++) {
                    const float* rc0 = r0 + c * (HI * WI);
                    const float* rc1 = r1 + c * (HI * WI);
                    const float v00 = __ldg(rc0 + x0c);
                    const float v10 = __ldg(rc1 + x0c);
                    const float v01 = __ldg(rc0 + x1c);
                    const float v11 = __ldg(rc1 + x1c);
                    const float rowA = v00 * wyv0 + v10 * wyv1;
                    const float rowB = v01 * wyv0 + v11 * wyv1;
                    const float s = rowA * wxv0 + rowB * wxv1;
                    A[c][j] = fmaf(wgt, s, A[c][j]);
                }
                T[j] *= (1.0f - m);
            }
        }
    }

    // Background contribution only where transparency survives.
    const float Tm = fmaxf(T[0], T[1]);
    if (Tm > 0.0f) {
        const float2 b0 = ldcs2(bg + base);
        const float2 b1 = ldcs2(bg + HW + base);
        const float2 b2 = ldcs2(bg + 2 * HW + base);
        A[0][0] = fmaf(b0.x, T[0], A[0][0]);
        A[0][1] = fmaf(b0.y, T[1], A[0][1]);
        A[1][0] = fmaf(b1.x, T[0], A[1][0]);
        A[1][1] = fmaf(b1.y, T[1], A[1][1]);
        A[2][0] = fmaf(b2.x, T[0], A[2][0]);
        A[2][1] = fmaf(b2.y, T[1], A[2][1]);
    }

    // Streaming stores: out is written once, never re-read.
    stcs2(out + base,          make_float2(A[0][0], A[0][1]));
    stcs2(out + HW + base,     make_float2(A[1][0], A[1][1]));
    stcs2(out + 2 * HW + base, make_float2(A[2][0], A[2][1]));
}

extern "C" void kernel_launch(void* const* d_in, const int* in_sizes, int n_in,
                              void* d_out, int out_size) {
    const float* src  = (const float*)d_in[0];  // [8,3,512,512]
    const float* bg   = (const float*)d_in[1];  // [1,3,2048,2048]
    const float* coor = (const float*)d_in[2];  // [8,4]
    float* out = (float*)d_out;                 // [1,3,2048,2048]

    dim3 block(32, 4);                    // 128 threads, warp = 64 px in x
    dim3 grid(WO / (2 * 32), HO / 4);     // (32, 512) = 16384 blocks
    composite_kernel<<<grid, block>>>(src, bg, coor, out);
}